// round 17
// baseline (speedup 1.0000x reference)
#include <cuda_runtime.h>
#include <cuda_fp16.h>
#include <cstdint>

// Local Scale Attention — round 14: attention processes 2 batches per CTA
// (384 thr, 12 warps) to amortize per-head barriers. GEMMs unchanged
// (round-13 proven 256-thr 128x128, 2-stage double buffer).
// B=2048, N=84, C=256, H=8, hd=32.

#define BATCH 2048
#define NTOK  84
#define DIM   256
#define HEADS 8
#define MROWS (BATCH * NTOK)            // 172032

__device__ __half g_xh   [(size_t)MROWS * 256];   //  88 MB
__device__ __half g_qkvh [(size_t)MROWS * 768];   // 264 MB
__device__ __half g_attnh[(size_t)MROWS * 256];   //  88 MB
__device__ __half g_WTh  [768 * 256];
__device__ __half g_WpTh [256 * 256];
__device__ float  g_bq   [768];
__device__ float  g_bias [HEADS * NTOK * NTOK];

// ---------------------------------------------------------------------------
__device__ __forceinline__ uint32_t smem_u32(const void* p) {
    uint32_t a;
    asm("{ .reg .u64 t; cvta.to.shared.u64 t, %1; cvt.u32.u64 %0, t; }" : "=r"(a) : "l"(p));
    return a;
}
__device__ __forceinline__ void cp_async16(uint32_t dst, const void* src) {
    asm volatile("cp.async.cg.shared.global [%0], [%1], 16;" :: "r"(dst), "l"(src));
}
__device__ __forceinline__ void mma_f16(float* d, const uint32_t* a, const uint32_t* b) {
    asm volatile(
        "mma.sync.aligned.m16n8k16.row.col.f32.f16.f16.f32 "
        "{%0,%1,%2,%3}, {%4,%5,%6,%7}, {%8,%9}, {%0,%1,%2,%3};"
        : "+f"(d[0]), "+f"(d[1]), "+f"(d[2]), "+f"(d[3])
        : "r"(a[0]), "r"(a[1]), "r"(a[2]), "r"(a[3]), "r"(b[0]), "r"(b[1]));
}
__device__ __forceinline__ uint32_t packh2(float a, float b) {
    __half2 h = __floats2half2_rn(a, b);
    return *reinterpret_cast<uint32_t*>(&h);
}

// ---------------------------------------------------------------------------
// prep kernels
// ---------------------------------------------------------------------------
__global__ void xprep_kernel(const float* __restrict__ x)
{
    size_t i = (size_t)blockIdx.x * 256 + threadIdx.x;   // float4 index
    float4 v = reinterpret_cast<const float4*>(x)[i];
    uint2 u;
    u.x = packh2(v.x, v.y);
    u.y = packh2(v.z, v.w);
    reinterpret_cast<uint2*>(g_xh)[i] = u;
}

__global__ void wprep_kernel(const float* __restrict__ Wqkv, const float* __restrict__ Wp,
                             const float* __restrict__ bqkv)
{
    int n = blockIdx.x, k = threadIdx.x;
    const float s = 0.10910894511799618f;   // 84^-0.5 folded into Q projection
    if (n < 768) {
        float f = (n < 256) ? s : 1.f;
        g_WTh[n * 256 + k] = __float2half_rn(Wqkv[k * 768 + n] * f);
        if (k == 0) g_bq[n] = bqkv[n] * f;
    } else {
        g_WpTh[(n - 768) * 256 + k] = __float2half_rn(Wp[k * 256 + (n - 768)]);
    }
}

__global__ void bias_kernel(const float* __restrict__ table, const int* __restrict__ ridx)
{
    int i = blockIdx.x * blockDim.x + threadIdx.x;
    if (i < NTOK * NTOK) {
        int r = ridx[i];
        #pragma unroll
        for (int h = 0; h < HEADS; ++h)
            g_bias[h * (NTOK * NTOK) + i] = table[r * HEADS + h];
    }
}

// ---------------------------------------------------------------------------
// fp16 GEMM (unchanged round-13): 256 thr, 128x128 CTA, 2-stage double
// buffer, ldmatrix fragments. 2 CTA/SM.
// ---------------------------------------------------------------------------
#define GEMM_SMEM 73728

template<bool OUT_FP16>
__global__ __launch_bounds__(256, 2)
void gemm_f16_kernel(const __half* __restrict__ A, const __half* __restrict__ BT,
                     const float* __restrict__ bias, void* __restrict__ outp, int ncols)
{
    extern __shared__ __half smh[];
    const uint32_t sb = smem_u32(smh);
    const int tid = threadIdx.x;
    const int w = tid >> 5, lane = tid & 31;
    const int g = lane >> 2, t = lane & 3;
    const int wm = w >> 1, wn = w & 1;
    const int n0 = blockIdx.x * 128;
    const int m0 = blockIdx.y * 128;

    const __half* Ab = A + (size_t)m0 * 256;
    const __half* Bb = BT + (size_t)n0 * 256;

    auto issue_load = [&](int kc, int stage) {
        uint32_t ab = sb + stage * (18432 * 2);
        uint32_t bb = ab + 9216 * 2;
        int k0 = kc * 64;
        #pragma unroll
        for (int it = 0; it < 4; ++it) {
            int idx = tid + it * 256;
            int r = idx >> 3, c = idx & 7;
            cp_async16(ab + (r * 72 + c * 8) * 2, Ab + (size_t)r * 256 + k0 + c * 8);
        }
        #pragma unroll
        for (int it = 0; it < 4; ++it) {
            int idx = tid + it * 256;
            int r = idx >> 3, c = idx & 7;
            cp_async16(bb + (r * 72 + c * 8) * 2, Bb + (size_t)r * 256 + k0 + c * 8);
        }
        asm volatile("cp.async.commit_group;" ::: "memory");
    };

    float d[2][8][4];
    #pragma unroll
    for (int i = 0; i < 2; ++i)
        #pragma unroll
        for (int j = 0; j < 8; ++j)
            #pragma unroll
            for (int q = 0; q < 4; ++q) d[i][j][q] = 0.f;

    const int arow  = lane & 15;
    const int akoff = (lane >> 4) * 8;
    const int bnrow = ((lane >> 4) << 3) + (lane & 7);
    const int bkoff = ((lane >> 3) & 1) * 8;

    auto compute = [&](int stage) {
        const uint32_t sAb = sb + stage * (18432 * 2);
        const uint32_t sBb = sAb + 9216 * 2;
        #pragma unroll
        for (int ks = 0; ks < 4; ++ks) {
            uint32_t a[2][4], bf[8][2];
            #pragma unroll
            for (int ii = 0; ii < 2; ++ii) {
                int row = wm * 32 + ii * 16 + arow;
                uint32_t addr = sAb + (row * 72 + ks * 16 + akoff) * 2;
                asm volatile(
                    "ldmatrix.sync.aligned.m8n8.x4.shared.b16 {%0,%1,%2,%3}, [%4];"
                    : "=r"(a[ii][0]), "=r"(a[ii][1]), "=r"(a[ii][2]), "=r"(a[ii][3])
                    : "r"(addr));
            }
            #pragma unroll
            for (int jp = 0; jp < 4; ++jp) {
                int n = wn * 64 + jp * 16 + bnrow;
                uint32_t addr = sBb + (n * 72 + ks * 16 + bkoff) * 2;
                asm volatile(
                    "ldmatrix.sync.aligned.m8n8.x4.shared.b16 {%0,%1,%2,%3}, [%4];"
                    : "=r"(bf[2 * jp][0]), "=r"(bf[2 * jp][1]),
                      "=r"(bf[2 * jp + 1][0]), "=r"(bf[2 * jp + 1][1])
                    : "r"(addr));
            }
            #pragma unroll
            for (int ii = 0; ii < 2; ++ii)
                #pragma unroll
                for (int j = 0; j < 8; ++j)
                    mma_f16(d[ii][j], a[ii], bf[j]);
        }
    };

    issue_load(0, 0);
    issue_load(1, 1);

    for (int i = 0; i < 4; ++i) {
        int buf = i & 1;
        if (i < 3) asm volatile("cp.async.wait_group 1;" ::: "memory");
        else       asm volatile("cp.async.wait_group 0;" ::: "memory");
        __syncthreads();
        compute(buf);
        __syncthreads();
        if (i + 2 < 4) issue_load(i + 2, buf);
    }

    #pragma unroll
    for (int ii = 0; ii < 2; ++ii) {
        int row = m0 + wm * 32 + ii * 16 + g;
        #pragma unroll
        for (int j = 0; j < 8; ++j) {
            int col = n0 + wn * 64 + j * 8 + 2 * t;
            float b0 = bias[col], b1 = bias[col + 1];
            if (OUT_FP16) {
                __half* oh = reinterpret_cast<__half*>(outp);
                uint32_t v0 = packh2(d[ii][j][0] + b0, d[ii][j][1] + b1);
                uint32_t v1 = packh2(d[ii][j][2] + b0, d[ii][j][3] + b1);
                *reinterpret_cast<uint32_t*>(oh + (size_t)row * ncols + col) = v0;
                *reinterpret_cast<uint32_t*>(oh + (size_t)(row + 8) * ncols + col) = v1;
            } else {
                float* of = reinterpret_cast<float*>(outp);
                *reinterpret_cast<float2*>(of + (size_t)row * ncols + col) =
                    make_float2(d[ii][j][0] + b0, d[ii][j][1] + b1);
                *reinterpret_cast<float2*>(of + (size_t)(row + 8) * ncols + col) =
                    make_float2(d[ii][j][2] + b0, d[ii][j][3] + b1);
            }
        }
    }
}

// ---------------------------------------------------------------------------
// attention: 2 batches per CTA. grid=1024, 384 thr (12 warps: 0-5 batch A,
// 6-11 batch B). Register softmax, ldmatrix.trans V, head double-buffering.
// smem: 2 buffers x 2 batch-slots x 11520 halves = 92160 B -> 2 CTA/SM.
// slot layout (halves): Q[96][40] @0, K[96][40] @3840, V[96][40] @7680.
// ---------------------------------------------------------------------------
#define ASLOT 11520
#define ABUF  (2 * ASLOT)                 // halves per buffer (2 batches)
#define ATTN_SMEM (2 * ABUF * 2)          // 92160 B

__global__ __launch_bounds__(384, 2)
void attn_kernel()
{
    extern __shared__ __half smh[];
    const uint32_t sb = smem_u32(smh);
    const int tid = threadIdx.x;
    const int w = tid >> 5, l = tid & 31;
    const int g = l >> 2, t = l & 3;
    const int wb = (w >= 6) ? 1 : 0;       // which batch slot
    const int wl = w - wb * 6;             // warp within batch (0..5)
    const size_t b0 = (size_t)blockIdx.x * 2;

    // zero V pad rows (keys 84..95) in all 4 slots once
    for (int i = tid; i < 480; i += 384) {
        int off = 7680 + (84 + i / 40) * 40 + (i % 40);
        smh[off] = __ushort_as_half(0);
        smh[ASLOT + off] = __ushort_as_half(0);
        smh[ABUF + off] = __ushort_as_half(0);
        smh[ABUF + ASLOT + off] = __ushort_as_half(0);
    }

    const __half* qb0 = g_qkvh + b0 * (NTOK * 768);

    auto issue_load = [&](int h, int buf) {
        uint32_t base = sb + buf * (ABUF * 2);
        for (int it = tid; it < 2016; it += 384) {
            int sl = it >= 1008;                      // batch slot
            int r = it - sl * 1008;
            int s = r / 336, rr = r - s * 336;
            int n = rr >> 2, c = rr & 3;
            cp_async16(base + (sl * ASLOT + s * 3840 + n * 40 + c * 8) * 2,
                       qb0 + (size_t)sl * (NTOK * 768) + (size_t)n * 768 + s * 256 + h * 32 + c * 8);
        }
        asm volatile("cp.async.commit_group;" ::: "memory");
    };

    issue_load(0, 0);
    int buf = 0;

    for (int h = 0; h < HEADS; ++h) {
        if (h + 1 < HEADS) {
            issue_load(h + 1, buf ^ 1);
            asm volatile("cp.async.wait_group 1;" ::: "memory");
        } else {
            asm volatile("cp.async.wait_group 0;" ::: "memory");
        }
        __syncthreads();

        const int slotw = buf * ABUF + wb * ASLOT;   // halves offset of my slot
        const uint32_t* sQw = reinterpret_cast<const uint32_t*>(smh + slotw);
        const uint32_t* sKw = reinterpret_cast<const uint32_t*>(smh + slotw + 3840);
        const uint32_t svb = sb + (slotw + 7680) * 2;

        float c4[12][4];
        #pragma unroll
        for (int ni = 0; ni < 12; ++ni)
            #pragma unroll
            for (int q = 0; q < 4; ++q) c4[ni][q] = 0.f;

        const int row = wl * 16 + g;
        #pragma unroll
        for (int ks = 0; ks < 2; ++ks) {
            uint32_t a[4];
            a[0] = sQw[ row      * 20 + ks * 8 + t];
            a[1] = sQw[(row + 8) * 20 + ks * 8 + t];
            a[2] = sQw[ row      * 20 + ks * 8 + t + 4];
            a[3] = sQw[(row + 8) * 20 + ks * 8 + t + 4];
            #pragma unroll
            for (int ni = 0; ni < 12; ++ni) {
                uint32_t bf[2];
                bf[0] = sKw[(ni * 8 + g) * 20 + ks * 8 + t];
                bf[1] = sKw[(ni * 8 + g) * 20 + ks * 8 + t + 4];
                mma_f16(c4[ni], a, bf);
            }
        }

        const int r0 = row, r1 = row + 8;
        const bool v0r = r0 < NTOK, v1r = r1 < NTOK;
        const float* gb = g_bias + h * (NTOK * NTOK);
        #pragma unroll
        for (int ni = 0; ni < 12; ++ni) {
            int col = ni * 8 + 2 * t;
            if (col < NTOK) {
                if (v0r) {
                    float2 f = *reinterpret_cast<const float2*>(gb + r0 * NTOK + col);
                    c4[ni][0] += f.x; c4[ni][1] += f.y;
                }
                if (v1r) {
                    float2 f = *reinterpret_cast<const float2*>(gb + r1 * NTOK + col);
                    c4[ni][2] += f.x; c4[ni][3] += f.y;
                }
            }
        }
        float m0 = -1e30f, m1 = -1e30f;
        #pragma unroll
        for (int ni = 0; ni < 12; ++ni) {
            int col = ni * 8 + 2 * t;
            if (col < NTOK) {
                m0 = fmaxf(m0, fmaxf(c4[ni][0], c4[ni][1]));
                m1 = fmaxf(m1, fmaxf(c4[ni][2], c4[ni][3]));
            }
        }
        m0 = fmaxf(m0, __shfl_xor_sync(0xffffffffu, m0, 1));
        m0 = fmaxf(m0, __shfl_xor_sync(0xffffffffu, m0, 2));
        m1 = fmaxf(m1, __shfl_xor_sync(0xffffffffu, m1, 1));
        m1 = fmaxf(m1, __shfl_xor_sync(0xffffffffu, m1, 2));
        float s0 = 0.f, s1 = 0.f;
        #pragma unroll
        for (int ni = 0; ni < 12; ++ni) {
            int col = ni * 8 + 2 * t;
            if (col < NTOK) {
                c4[ni][0] = __expf(c4[ni][0] - m0);
                c4[ni][1] = __expf(c4[ni][1] - m0);
                c4[ni][2] = __expf(c4[ni][2] - m1);
                c4[ni][3] = __expf(c4[ni][3] - m1);
                s0 += c4[ni][0] + c4[ni][1];
                s1 += c4[ni][2] + c4[ni][3];
            } else {
                c4[ni][0] = c4[ni][1] = c4[ni][2] = c4[ni][3] = 0.f;
            }
        }
        s0 += __shfl_xor_sync(0xffffffffu, s0, 1);
        s0 += __shfl_xor_sync(0xffffffffu, s0, 2);
        s1 += __shfl_xor_sync(0xffffffffu, s1, 1);
        s1 += __shfl_xor_sync(0xffffffffu, s1, 2);
        const float i0 = 1.f / s0, i1 = 1.f / s1;
        #pragma unroll
        for (int ni = 0; ni < 12; ++ni) {
            c4[ni][0] *= i0; c4[ni][1] *= i0;
            c4[ni][2] *= i1; c4[ni][3] *= i1;
        }

        float o[4][4];
        #pragma unroll
        for (int nj = 0; nj < 4; ++nj)
            #pragma unroll
            for (int q = 0; q < 4; ++q) o[nj][q] = 0.f;

        #pragma unroll
        for (int ks = 0; ks < 6; ++ks) {
            uint32_t a[4];
            a[0] = packh2(c4[2 * ks][0],     c4[2 * ks][1]);
            a[1] = packh2(c4[2 * ks][2],     c4[2 * ks][3]);
            a[2] = packh2(c4[2 * ks + 1][0], c4[2 * ks + 1][1]);
            a[3] = packh2(c4[2 * ks + 1][2], c4[2 * ks + 1][3]);
            #pragma unroll
            for (int njp = 0; njp < 2; ++njp) {
                uint32_t r0m, r1m, r2m, r3m;
                uint32_t addr = svb +
                    (((ks * 16 + (l & 15)) * 40) + (njp * 2 + (l >> 4)) * 8) * 2;
                asm volatile(
                    "ldmatrix.sync.aligned.m8n8.x4.trans.shared.b16 {%0,%1,%2,%3}, [%4];"
                    : "=r"(r0m), "=r"(r1m), "=r"(r2m), "=r"(r3m) : "r"(addr));
                uint32_t bf0[2] = {r0m, r1m};
                uint32_t bf1[2] = {r2m, r3m};
                mma_f16(o[njp * 2],     a, bf0);
                mma_f16(o[njp * 2 + 1], a, bf1);
            }
        }

        __half* oa = g_attnh + (b0 + wb) * (NTOK * 256) + h * 32;
        #pragma unroll
        for (int nj = 0; nj < 4; ++nj) {
            int col = nj * 8 + 2 * t;
            if (v0r)
                *reinterpret_cast<uint32_t*>(oa + (size_t)r0 * 256 + col) =
                    packh2(o[nj][0], o[nj][1]);
            if (v1r)
                *reinterpret_cast<uint32_t*>(oa + (size_t)r1 * 256 + col) =
                    packh2(o[nj][2], o[nj][3]);
        }

        __syncthreads();
        buf ^= 1;
    }
}

// ---------------------------------------------------------------------------
extern "C" void kernel_launch(void* const* d_in, const int* in_sizes, int n_in,
                              void* d_out, int out_size)
{
    const float* x     = (const float*)d_in[0];
    const float* Wqkv  = (const float*)d_in[1];
    const float* bqkv  = (const float*)d_in[2];
    const float* Wp    = (const float*)d_in[3];
    const float* bp    = (const float*)d_in[4];
    const float* table = (const float*)d_in[5];
    const int*   ridx  = (const int*)d_in[6];
    float* out = (float*)d_out;

    cudaFuncSetAttribute(gemm_f16_kernel<true>,  cudaFuncAttributeMaxDynamicSharedMemorySize, GEMM_SMEM);
    cudaFuncSetAttribute(gemm_f16_kernel<false>, cudaFuncAttributeMaxDynamicSharedMemorySize, GEMM_SMEM);
    cudaFuncSetAttribute(attn_kernel, cudaFuncAttributeMaxDynamicSharedMemorySize, ATTN_SMEM);

    __half* xh;   cudaGetSymbolAddress((void**)&xh,   g_xh);
    __half* qkvh; cudaGetSymbolAddress((void**)&qkvh, g_qkvh);
    __half* ath;  cudaGetSymbolAddress((void**)&ath,  g_attnh);
    __half* wth;  cudaGetSymbolAddress((void**)&wth,  g_WTh);
    __half* wpth; cudaGetSymbolAddress((void**)&wpth, g_WpTh);
    float*  bq;   cudaGetSymbolAddress((void**)&bq,   g_bq);

    xprep_kernel<<<MROWS / 4, 256>>>(x);
    wprep_kernel<<<1024, 256>>>(Wqkv, Wp, bqkv);
    bias_kernel<<<28, 256>>>(table, ridx);
    gemm_f16_kernel<true><<<dim3(6, 1344), 256, GEMM_SMEM>>>(xh, wth, bq, qkvh, 768);
    attn_kernel<<<BATCH / 2, 384, ATTN_SMEM>>>();
    gemm_f16_kernel<false><<<dim3(2, 1344), 256, GEMM_SMEM>>>(ath, wpth, bp, out, 256);
}